// round 10
// baseline (speedup 1.0000x reference)
#include <cuda_runtime.h>
#include <math.h>

#define SEQ 40
#define HID 128
#define WARPS 9
#define TPB (WARPS * 32)      // 288 x 2 CTAs -> 18 warps/SM, reg cap 113
#define NCTA 296              // 148 SMs x 2 CTAs
#define ROWS (HID + 8)        // 128 w_rec rows + 8 w_in channel rows

// Lane-permuted weight tile (R4 layout):
//  row j (<128):   g_wT[j*128 + 4*lane + k] = w_rec[(32*k+lane)*128 + j]
//  row 128+ch:     g_wT[(128+ch)*128 + 4*lane + k] = w_in[(32*k+lane)*8 + ch]
__device__ float g_wT[ROWS * HID];
__device__ int g_ctr;

__global__ void prep_kernel(const float* __restrict__ w_rec,
                            const float* __restrict__ w_in) {
    int tid = blockIdx.x * blockDim.x + threadIdx.x;
    if (tid == 0) g_ctr = 0;
    if (tid < HID * HID) {
        int h = tid >> 7, j = tid & 127;
        g_wT[j * HID + ((h & 31) << 2) + (h >> 5)] = w_rec[tid];
    } else if (tid < HID * HID + HID * 8) {
        int r = tid - HID * HID;
        int h = r >> 3, ch = r & 7;
        g_wT[(HID + ch) * HID + ((h & 31) << 2) + (h >> 5)] = w_in[r];
    }
}

// ---- packed f32x2 helpers (sm_103a) ----
__device__ __forceinline__ unsigned long long pk2(float a, float b) {
    unsigned long long r;
    asm("mov.b64 %0, {%1, %2};" : "=l"(r) : "f"(a), "f"(b));
    return r;
}
__device__ __forceinline__ void upk2(unsigned long long v, float& a, float& b) {
    asm("mov.b64 {%0, %1}, %2;" : "=f"(a), "=f"(b) : "l"(v));
}
__device__ __forceinline__ unsigned long long addx2(unsigned long long a,
                                                    unsigned long long b) {
    unsigned long long r;
    asm("add.rn.f32x2 %0, %1, %2;" : "=l"(r) : "l"(a), "l"(b));
    return r;
}

__global__ __launch_bounds__(TPB, 2) void snn_kernel(
    const float* __restrict__ x,       // (B, 4)
    const float* __restrict__ w_out,   // (2, 128)
    const float* __restrict__ mask,    // (40, B, 128)
    float* __restrict__ out,           // (B, 2)
    int B)
{
    extern __shared__ ulonglong2 srec[];   // [ROWS][32 lanes] 16B = 68 KB

    {   // stage weights once per (persistent) CTA: coalesced, conflict-free
        const ulonglong2* src = reinterpret_cast<const ulonglong2*>(g_wT);
        for (int i = threadIdx.x; i < ROWS * 32; i += TPB)
            srec[i] = src[i];
    }
    __syncthreads();

    const int lane = threadIdx.x & 31;
    const size_t mstride = (size_t)B * HID;

    // lane-dependent readout weights (shared by both streams)
    float wo0[4], wo1[4];
    #pragma unroll
    for (int k = 0; k < 4; k++) {
        int h = 32 * k + lane;
        wo0[k] = w_out[h];
        wo1[k] = w_out[HID + h];
    }

    for (;;) {
        // ---- per-warp work stealing: TWO batch elements per grab ----
        int b;
        if (lane == 0) b = atomicAdd(&g_ctr, 2);
        b = __shfl_sync(0xffffffffu, b, 0);
        if (b >= B) break;
        const int bA = b;
        const int bB = (b + 1 < B) ? (b + 1) : b;   // dup-safe if B odd

        // ---- encoder constants per stream (warp-uniform) ----
        float cA[4], vencA[4], cB[4], vencB[4];
        int rowA[4], rowB[4];
        #pragma unroll
        for (int f = 0; f < 4; f++) {
            float xa = x[(size_t)bA * 4 + f];
            rowA[f] = (HID + ((xa > 0.0f) ? f : (f + 4))) * 32;
            cA[f] = 50.0f * fabsf(xa);
            vencA[f] = 0.0f;
            float xb = x[(size_t)bB * 4 + f];
            rowB[f] = (HID + ((xb > 0.0f) ? f : (f + 4))) * 32;
            cB[f] = 50.0f * fabsf(xb);
            vencB[f] = 0.0f;
        }

        // ---- state per stream: lane owns hidden neurons h = 32k + lane ----
        float vA[4]   = {0.f, 0.f, 0.f, 0.f};
        float curA[4] = {0.f, 0.f, 0.f, 0.f};
        float vB[4]   = {0.f, 0.f, 0.f, 0.f};
        float curB[4] = {0.f, 0.f, 0.f, 0.f};
        float voA0 = 0.f, ioA0 = 0.f, voA1 = 0.f, ioA1 = 0.f;
        float voB0 = 0.f, ioB0 = 0.f, voB1 = 0.f, ioB1 = 0.f;
        float mA0 = -1e30f, mA1 = -1e30f, mB0 = -1e30f, mB1 = -1e30f;
        unsigned zbA[4] = {0u, 0u, 0u, 0u};
        unsigned zbB[4] = {0u, 0u, 0u, 0u};

        const float* mrowA = mask + (size_t)bA * HID + lane;
        const float* mrowB = mask + (size_t)bB * HID + lane;
        float pmA[4], pmB[4];
        #pragma unroll
        for (int k = 0; k < 4; k++) {
            pmA[k] = __ldcs(mrowA + 32 * k);
            pmB[k] = __ldcs(mrowB + 32 * k);
        }

        for (int t = 0; t < SEQ; t++) {
            // ---- prefetch next step's mask rows (overlap whole iteration) ----
            const float* nrowA = (t < SEQ - 1) ? (mrowA + mstride) : mrowA;
            const float* nrowB = (t < SEQ - 1) ? (mrowB + mstride) : mrowB;
            float pnA[4], pnB[4];
            #pragma unroll
            for (int k = 0; k < 4; k++) {
                pnA[k] = __ldcs(nrowA + 32 * k);
                pnB[k] = __ldcs(nrowB + 32 * k);
            }

            // ---- encoder LIF steps (warp-uniform spikes) ----
            bool esA[4], esB[4];
            #pragma unroll
            for (int f = 0; f < 4; f++) {
                float vd = fmaf(0.1f, cA[f] - vencA[f], vencA[f]);
                esA[f] = vd > 1.0f;
                vencA[f] = esA[f] ? 0.0f : vd;
                float ve = fmaf(0.1f, cB[f] - vencB[f], vencB[f]);
                esB[f] = ve > 1.0f;
                vencB[f] = esB[f] ? 0.0f : ve;
            }

            // ---- recurrent LIF membrane updates ----
            bool znA[4], znB[4];
            #pragma unroll
            for (int k = 0; k < 4; k++) {
                float vd = fmaf(0.1f, curA[k] - vA[k], vA[k]);
                znA[k] = vd > 1.0f;
                vA[k] = znA[k] ? 0.0f : vd;
                curA[k] *= 0.8f;
                float ve = fmaf(0.1f, curB[k] - vB[k], vB[k]);
                znB[k] = ve > 1.0f;
                vB[k] = znB[k] ? 0.0f : ve;
                curB[k] *= 0.8f;
            }

            // ---- sparse current accumulation: one packed pair per stream ----
            unsigned long long cA01 = pk2(curA[0], curA[1]);
            unsigned long long cA23 = pk2(curA[2], curA[3]);
            unsigned long long cB01 = pk2(curB[0], curB[1]);
            unsigned long long cB23 = pk2(curB[2], curB[3]);

            // input channel rows (warp-uniform predicates, independent loads)
            #pragma unroll
            for (int f = 0; f < 4; f++) {
                if (esA[f]) {
                    ulonglong2 w = srec[rowA[f] + lane];
                    cA01 = addx2(cA01, w.x);
                    cA23 = addx2(cA23, w.y);
                }
                if (esB[f]) {
                    ulonglong2 w = srec[rowB[f] + lane];
                    cB01 = addx2(cB01, w.x);
                    cB23 = addx2(cB23, w.y);
                }
            }

            // recurrent rows: merged dual-stream loop. Both streams read the
            // same weight tile, so each iteration issues TWO independent
            // LDS.128 (2x MLP) feeding independent accumulator chains.
            #pragma unroll
            for (int k = 0; k < 4; k++) {
                unsigned ba = zbA[k], bb = zbB[k];
                const ulonglong2* rowp = srec + (32 * k) * 32 + lane;
                while (ba && bb) {
                    int ja = __ffs(ba) - 1; ba &= ba - 1;
                    int jb = __ffs(bb) - 1; bb &= bb - 1;
                    ulonglong2 wa = rowp[ja * 32];
                    ulonglong2 wb = rowp[jb * 32];
                    cA01 = addx2(cA01, wa.x);
                    cA23 = addx2(cA23, wa.y);
                    cB01 = addx2(cB01, wb.x);
                    cB23 = addx2(cB23, wb.y);
                }
                while (ba) {   // tail A (2-unrolled load issue)
                    int j1 = __ffs(ba) - 1; ba &= ba - 1;
                    ulonglong2 w1 = rowp[j1 * 32];
                    if (ba) {
                        int j2 = __ffs(ba) - 1; ba &= ba - 1;
                        ulonglong2 w2 = rowp[j2 * 32];
                        cA01 = addx2(cA01, w2.x);
                        cA23 = addx2(cA23, w2.y);
                    }
                    cA01 = addx2(cA01, w1.x);
                    cA23 = addx2(cA23, w1.y);
                }
                while (bb) {   // tail B
                    int j1 = __ffs(bb) - 1; bb &= bb - 1;
                    ulonglong2 w1 = rowp[j1 * 32];
                    if (bb) {
                        int j2 = __ffs(bb) - 1; bb &= bb - 1;
                        ulonglong2 w2 = rowp[j2 * 32];
                        cB01 = addx2(cB01, w2.x);
                        cB23 = addx2(cB23, w2.y);
                    }
                    cB01 = addx2(cB01, w1.x);
                    cB23 = addx2(cB23, w1.y);
                }
            }
            upk2(cA01, curA[0], curA[1]);
            upk2(cA23, curA[2], curA[3]);
            upk2(cB01, curB[0], curB[1]);
            upk2(cB23, curB[2], curB[3]);

            // ---- publish new spikes ----
            #pragma unroll
            for (int k = 0; k < 4; k++) {
                zbA[k] = __ballot_sync(0xffffffffu, znA[k]);
                zbB[k] = __ballot_sync(0xffffffffu, znB[k]);
            }

            // ---- readout drives ----
            float dA0 = 0.f, dA1 = 0.f, dB0 = 0.f, dB1 = 0.f;
            #pragma unroll
            for (int k = 0; k < 4; k++) {
                float ma = znA[k] ? pmA[k] : 0.0f;
                dA0 = fmaf(ma, wo0[k], dA0);
                dA1 = fmaf(ma, wo1[k], dA1);
                float mb = znB[k] ? pmB[k] : 0.0f;
                dB0 = fmaf(mb, wo0[k], dB0);
                dB1 = fmaf(mb, wo1[k], dB1);
            }
            // two interleaved packed butterflies: latency overlaps
            unsigned long long dA = pk2(dA0, dA1);
            unsigned long long dB = pk2(dB0, dB1);
            #pragma unroll
            for (int off = 16; off; off >>= 1) {
                unsigned long long sa = __shfl_xor_sync(0xffffffffu, dA, off);
                unsigned long long sb = __shfl_xor_sync(0xffffffffu, dB, off);
                dA = addx2(dA, sa);
                dB = addx2(dB, sb);
            }
            upk2(dA, dA0, dA1);
            upk2(dB, dB0, dB1);

            // ---- LI readouts (vo uses OLD io, matching reference) ----
            voA0 = fmaf(0.1f, ioA0 - voA0, voA0);
            voA1 = fmaf(0.1f, ioA1 - voA1, voA1);
            ioA0 = fmaf(0.8f, ioA0, dA0);
            ioA1 = fmaf(0.8f, ioA1, dA1);
            mA0 = fmaxf(mA0, voA0);
            mA1 = fmaxf(mA1, voA1);
            voB0 = fmaf(0.1f, ioB0 - voB0, voB0);
            voB1 = fmaf(0.1f, ioB1 - voB1, voB1);
            ioB0 = fmaf(0.8f, ioB0, dB0);
            ioB1 = fmaf(0.8f, ioB1, dB1);
            mB0 = fmaxf(mB0, voB0);
            mB1 = fmaxf(mB1, voB1);

            #pragma unroll
            for (int k = 0; k < 4; k++) {
                pmA[k] = pnA[k];
                pmB[k] = pnB[k];
            }
            mrowA = nrowA;
            mrowB = nrowB;
        }

        if (lane == 0) {
            float mm = fmaxf(mA0, mA1);
            float e0 = expf(mA0 - mm);
            float e1 = expf(mA1 - mm);
            float inv = 1.0f / (e0 + e1);
            out[(size_t)bA * 2 + 0] = e0 * inv;
            out[(size_t)bA * 2 + 1] = e1 * inv;
            if (bB != bA) {
                float nn = fmaxf(mB0, mB1);
                float f0 = expf(mB0 - nn);
                float f1 = expf(mB1 - nn);
                float jnv = 1.0f / (f0 + f1);
                out[(size_t)bB * 2 + 0] = f0 * jnv;
                out[(size_t)bB * 2 + 1] = f1 * jnv;
            }
        }
    }
}

extern "C" void kernel_launch(void* const* d_in, const int* in_sizes, int n_in,
                              void* d_out, int out_size) {
    const float* x     = (const float*)d_in[0];  // (B, 4)
    const float* w_in  = (const float*)d_in[1];  // (128, 8)
    const float* w_rec = (const float*)d_in[2];  // (128, 128)
    const float* w_out = (const float*)d_in[3];  // (2, 128)
    const float* mask  = (const float*)d_in[4];  // (40, B, 128)
    float* out = (float*)d_out;

    const int B = in_sizes[0] / 4;

    cudaFuncSetAttribute(snn_kernel,
                         cudaFuncAttributeMaxDynamicSharedMemorySize,
                         ROWS * HID * (int)sizeof(float));

    prep_kernel<<<(HID * HID + HID * 8 + 255) / 256, 256>>>(w_rec, w_in);

    snn_kernel<<<NCTA, TPB, ROWS * HID * sizeof(float)>>>(
        x, w_out, mask, out, B);
}

// round 11
// speedup vs baseline: 1.0706x; 1.0706x over previous
#include <cuda_runtime.h>
#include <math.h>

#define SEQ 40
#define HID 128
#define WARPS 9
#define TPB (WARPS * 32)      // 288 x 3 CTAs -> 27 warps/SM, reg cap 75 (known-best config)
#define NCTA 444              // 148 SMs x 3 CTAs
#define ROWS (HID + 8)        // 128 w_rec rows + 8 w_in channel rows

// Lane-permuted weight tile (R4 layout):
//  row j (<128):   g_wT[j*128 + 4*lane + k] = w_rec[(32*k+lane)*128 + j]
//  row 128+ch:     g_wT[(128+ch)*128 + 4*lane + k] = w_in[(32*k+lane)*8 + ch]
__device__ float g_wT[ROWS * HID];
__device__ int g_ctr;

__global__ void prep_kernel(const float* __restrict__ w_rec,
                            const float* __restrict__ w_in) {
    int tid = blockIdx.x * blockDim.x + threadIdx.x;
    if (tid == 0) g_ctr = 0;
    if (tid < HID * HID) {
        int h = tid >> 7, j = tid & 127;
        g_wT[j * HID + ((h & 31) << 2) + (h >> 5)] = w_rec[tid];
    } else if (tid < HID * HID + HID * 8) {
        int r = tid - HID * HID;
        int h = r >> 3, ch = r & 7;
        g_wT[(HID + ch) * HID + ((h & 31) << 2) + (h >> 5)] = w_in[r];
    }
}

// ---- packed f32x2 helpers (sm_103a) ----
__device__ __forceinline__ unsigned long long pk2(float a, float b) {
    unsigned long long r;
    asm("mov.b64 %0, {%1, %2};" : "=l"(r) : "f"(a), "f"(b));
    return r;
}
__device__ __forceinline__ void upk2(unsigned long long v, float& a, float& b) {
    asm("mov.b64 {%0, %1}, %2;" : "=f"(a), "=f"(b) : "l"(v));
}
__device__ __forceinline__ unsigned long long addx2(unsigned long long a,
                                                    unsigned long long b) {
    unsigned long long r;
    asm("add.rn.f32x2 %0, %1, %2;" : "=l"(r) : "l"(a), "l"(b));
    return r;
}

__global__ __launch_bounds__(TPB, 3) void snn_kernel(
    const float* __restrict__ x,       // (B, 4)
    const float* __restrict__ w_out,   // (2, 128)
    const float* __restrict__ mask,    // (40, B, 128)
    float* __restrict__ out,           // (B, 2)
    int B)
{
    extern __shared__ ulonglong2 srec[];   // [ROWS][32 lanes] 16B = 68 KB

    {   // stage weights once per (persistent) CTA: coalesced, conflict-free
        const ulonglong2* src = reinterpret_cast<const ulonglong2*>(g_wT);
        for (int i = threadIdx.x; i < ROWS * 32; i += TPB)
            srec[i] = src[i];
    }
    __syncthreads();

    const int lane = threadIdx.x & 31;
    const size_t mstride = (size_t)B * HID;

    // lane-dependent readout weights: hoisted out of the work loop
    float wo0[4], wo1[4];
    #pragma unroll
    for (int k = 0; k < 4; k++) {
        int h = 32 * k + lane;
        wo0[k] = w_out[h];
        wo1[k] = w_out[HID + h];
    }

    for (;;) {
        // ---- per-warp work stealing: one batch element per grab ----
        int b;
        if (lane == 0) b = atomicAdd(&g_ctr, 1);
        b = __shfl_sync(0xffffffffu, b, 0);
        if (b >= B) break;

        // ---- encoder constants (warp-uniform) ----
        float c_in[4], venc[4];
        int rowe[4];     // srec element index of this feature's w_in row
        #pragma unroll
        for (int f = 0; f < 4; f++) {
            float xv = x[(size_t)b * 4 + f];
            int ch = (xv > 0.0f) ? f : (f + 4);
            rowe[f] = (HID + ch) * 32;
            c_in[f] = 50.0f * fabsf(xv);
            venc[f] = 0.0f;
        }

        // ---- state: lane owns hidden neurons h = 32k + lane ----
        float v[4]   = {0.f, 0.f, 0.f, 0.f};
        float cur[4] = {0.f, 0.f, 0.f, 0.f};
        float vo0 = 0.f, io0 = 0.f, vo1 = 0.f, io1 = 0.f;
        float m0 = -1e30f, m1 = -1e30f;
        unsigned zb[4] = {0u, 0u, 0u, 0u};

        // per-lane UNREDUCED readout drive of the previous step (packed).
        // Reduced one iteration late: vo_t only needs io_{t-1}, which needs
        // d_{t-1}; so the butterfly for d_{t-1} runs at the top of iter t and
        // its latency is hidden by the whole spike loop. d_{SEQ-1} is never
        // observed (would only feed vo_SEQ), so its reduction is skipped.
        unsigned long long dprev = 0ull;

        const float* mrow = mask + (size_t)b * HID + lane;
        float pm[4];
        #pragma unroll
        for (int k = 0; k < 4; k++) pm[k] = __ldcs(mrow + 32 * k);

        #pragma unroll 2
        for (int t = 0; t < SEQ; t++) {
            // ---- start butterfly reduction of d_{t-1} (consumed after the
            //      spike loop below; its 5x26cyc chain overlaps the LDS work) ----
            unsigned long long red = dprev;
            #pragma unroll
            for (int off = 16; off; off >>= 1)
                red = addx2(red, __shfl_xor_sync(0xffffffffu, red, off));

            // ---- prefetch next step's mask row ----
            const float* nrow = (t < SEQ - 1) ? (mrow + mstride) : mrow;
            float pn[4];
            #pragma unroll
            for (int k = 0; k < 4; k++) pn[k] = __ldcs(nrow + 32 * k);

            // ---- encoder LIF step (warp-uniform spikes) ----
            bool es[4];
            #pragma unroll
            for (int f = 0; f < 4; f++) {
                float vd = fmaf(0.1f, c_in[f] - venc[f], venc[f]);
                es[f] = vd > 1.0f;
                venc[f] = es[f] ? 0.0f : vd;
            }

            // ---- recurrent LIF membrane update ----
            bool zn[4];
            #pragma unroll
            for (int k = 0; k < 4; k++) {
                float vd = fmaf(0.1f, cur[k] - v[k], v[k]);
                zn[k] = vd > 1.0f;
                v[k] = zn[k] ? 0.0f : vd;
                cur[k] *= 0.8f;
            }

            // ---- sparse current accumulation, dual packed accumulators ----
            unsigned long long c01  = pk2(cur[0], cur[1]);
            unsigned long long c23  = pk2(cur[2], cur[3]);
            unsigned long long c01b = 0ull;   // packed {0.f, 0.f}
            unsigned long long c23b = 0ull;

            // input channel rows (warp-uniform predicates)
            #pragma unroll
            for (int f = 0; f < 4; f++) {
                if (es[f]) {
                    ulonglong2 w = srec[rowe[f] + lane];
                    c01 = addx2(c01, w.x);
                    c23 = addx2(c23, w.y);
                }
            }
            // recurrent rows over z_prev; bits warp-uniform (ballot), so the
            // control flow is non-divergent. Unroll-by-2: both LDS.128 issue
            // before their dependent adds (2x MLP in the hot loop).
            #pragma unroll
            for (int k = 0; k < 4; k++) {
                unsigned bits = zb[k];
                const ulonglong2* rowp = srec + (32 * k) * 32 + lane;
                while (bits) {
                    int j1 = __ffs(bits) - 1; bits &= bits - 1;
                    ulonglong2 w1 = rowp[j1 * 32];
                    if (bits) {
                        int j2 = __ffs(bits) - 1; bits &= bits - 1;
                        ulonglong2 w2 = rowp[j2 * 32];
                        c01b = addx2(c01b, w2.x);
                        c23b = addx2(c23b, w2.y);
                    }
                    c01 = addx2(c01, w1.x);
                    c23 = addx2(c23, w1.y);
                }
            }
            c01 = addx2(c01, c01b);
            c23 = addx2(c23, c23b);
            upk2(c01, cur[0], cur[1]);
            upk2(c23, cur[2], cur[3]);

            // ---- publish new spikes ----
            #pragma unroll
            for (int k = 0; k < 4; k++)
                zb[k] = __ballot_sync(0xffffffffu, zn[k]);

            // ---- finalize io_{t-1} with the now-reduced d_{t-1}, then vo_t ----
            float r0, r1;
            upk2(red, r0, r1);
            io0 = fmaf(0.8f, io0, r0);            // io_{t-1} = 0.8*io_{t-2} + d_{t-1}
            io1 = fmaf(0.8f, io1, r1);
            vo0 = fmaf(0.1f, io0 - vo0, vo0);     // vo_t uses io_{t-1} (reference order)
            vo1 = fmaf(0.1f, io1 - vo1, vo1);
            m0 = fmaxf(m0, vo0);
            m1 = fmaxf(m1, vo1);

            // ---- per-lane readout drive d_t: (z_new * mask) @ w_out.T ----
            float d0 = 0.f, d1 = 0.f;
            #pragma unroll
            for (int k = 0; k < 4; k++) {
                float mv = zn[k] ? pm[k] : 0.0f;
                d0 = fmaf(mv, wo0[k], d0);
                d1 = fmaf(mv, wo1[k], d1);
            }
            dprev = pk2(d0, d1);   // reduced at the top of the next iteration

            #pragma unroll
            for (int k = 0; k < 4; k++) pm[k] = pn[k];
            mrow = nrow;
        }

        if (lane == 0) {
            float mm = fmaxf(m0, m1);
            float e0 = expf(m0 - mm);
            float e1 = expf(m1 - mm);
            float inv = 1.0f / (e0 + e1);
            out[(size_t)b * 2 + 0] = e0 * inv;
            out[(size_t)b * 2 + 1] = e1 * inv;
        }
    }
}

extern "C" void kernel_launch(void* const* d_in, const int* in_sizes, int n_in,
                              void* d_out, int out_size) {
    const float* x     = (const float*)d_in[0];  // (B, 4)
    const float* w_in  = (const float*)d_in[1];  // (128, 8)
    const float* w_rec = (const float*)d_in[2];  // (128, 128)
    const float* w_out = (const float*)d_in[3];  // (2, 128)
    const float* mask  = (const float*)d_in[4];  // (40, B, 128)
    float* out = (float*)d_out;

    const int B = in_sizes[0] / 4;

    cudaFuncSetAttribute(snn_kernel,
                         cudaFuncAttributeMaxDynamicSharedMemorySize,
                         ROWS * HID * (int)sizeof(float));

    prep_kernel<<<(HID * HID + HID * 8 + 255) / 256, 256>>>(w_rec, w_in);

    snn_kernel<<<NCTA, TPB, ROWS * HID * sizeof(float)>>>(
        x, w_out, mask, out, B);
}

// round 12
// speedup vs baseline: 1.1445x; 1.0690x over previous
#include <cuda_runtime.h>
#include <math.h>

#define SEQ 40
#define HID 128
#define WARPS 9
#define TPB (WARPS * 32)      // 288 x 3 CTAs -> 27 warps/SM (best measured config)
#define NCTA 444              // 148 SMs x 3 CTAs
#define ROWS (HID + 8)        // 128 w_rec rows + 8 w_in channel rows

// Lane-permuted weight tile:
//  row j (<128):   g_wT[j*128 + 4*lane + k] = w_rec[(32*k+lane)*128 + j]
//  row 128+ch:     g_wT[(128+ch)*128 + 4*lane + k] = w_in[(32*k+lane)*8 + ch]
__device__ float g_wT[ROWS * HID];
__device__ int g_ctr;

__global__ void prep_kernel(const float* __restrict__ w_rec,
                            const float* __restrict__ w_in) {
    int tid = blockIdx.x * blockDim.x + threadIdx.x;
    if (tid == 0) g_ctr = 0;
    if (tid < HID * HID) {
        int h = tid >> 7, j = tid & 127;
        g_wT[j * HID + ((h & 31) << 2) + (h >> 5)] = w_rec[tid];
    } else if (tid < HID * HID + HID * 8) {
        int r = tid - HID * HID;
        int h = r >> 3, ch = r & 7;
        g_wT[(HID + ch) * HID + ((h & 31) << 2) + (h >> 5)] = w_in[r];
    }
}

// ---- packed f32x2 helpers (sm_103a) ----
__device__ __forceinline__ unsigned long long pk2(float a, float b) {
    unsigned long long r;
    asm("mov.b64 %0, {%1, %2};" : "=l"(r) : "f"(a), "f"(b));
    return r;
}
__device__ __forceinline__ void upk2(unsigned long long v, float& a, float& b) {
    asm("mov.b64 {%0, %1}, %2;" : "=f"(a), "=f"(b) : "l"(v));
}
__device__ __forceinline__ unsigned long long addx2(unsigned long long a,
                                                    unsigned long long b) {
    unsigned long long r;
    asm("add.rn.f32x2 %0, %1, %2;" : "=l"(r) : "l"(a), "l"(b));
    return r;
}

__global__ __launch_bounds__(TPB, 3) void snn_kernel(
    const float* __restrict__ x,       // (B, 4)
    const float* __restrict__ w_out,   // (2, 128)
    const float* __restrict__ mask,    // (40, B, 128)
    float* __restrict__ out,           // (B, 2)
    int B)
{
    extern __shared__ ulonglong2 srec[];   // [ROWS][32 lanes] 16B = 68 KB

    {   // stage weights once per (persistent) CTA: coalesced, conflict-free
        const ulonglong2* src = reinterpret_cast<const ulonglong2*>(g_wT);
        for (int i = threadIdx.x; i < ROWS * 32; i += TPB)
            srec[i] = src[i];
    }
    __syncthreads();

    const int lane = threadIdx.x & 31;
    const size_t mstride = (size_t)B * HID;

    // lane-dependent readout weights: hoisted out of the work loop
    float wo0[4], wo1[4];
    #pragma unroll
    for (int k = 0; k < 4; k++) {
        int h = 32 * k + lane;
        wo0[k] = w_out[h];
        wo1[k] = w_out[HID + h];
    }

    for (;;) {
        // ---- per-warp work stealing: one batch element per grab ----
        int b;
        if (lane == 0) b = atomicAdd(&g_ctr, 1);
        b = __shfl_sync(0xffffffffu, b, 0);
        if (b >= B) break;

        // ---- encoder constants (warp-uniform) ----
        float c_in[4], venc[4];
        int rowe[4];     // srec element index of this feature's w_in row
        #pragma unroll
        for (int f = 0; f < 4; f++) {
            float xv = x[(size_t)b * 4 + f];
            int ch = (xv > 0.0f) ? f : (f + 4);
            rowe[f] = (HID + ch) * 32;
            c_in[f] = 50.0f * fabsf(xv);
            venc[f] = 0.0f;
        }

        // ---- state: lane owns hidden neurons h = 32k + lane ----
        float v[4]   = {0.f, 0.f, 0.f, 0.f};
        float cur[4] = {0.f, 0.f, 0.f, 0.f};
        float vo0 = 0.f, io0 = 0.f, vo1 = 0.f, io1 = 0.f;
        float m0 = -1e30f, m1 = -1e30f;
        unsigned zb[4] = {0u, 0u, 0u, 0u};

        const float* mrow = mask + (size_t)b * HID + lane;
        float pm[4];
        #pragma unroll
        for (int k = 0; k < 4; k++) pm[k] = __ldcs(mrow + 32 * k);

        #pragma unroll 2
        for (int t = 0; t < SEQ; t++) {
            // ---- prefetch next step's mask row ----
            const float* nrow = (t < SEQ - 1) ? (mrow + mstride) : mrow;
            float pn[4];
            #pragma unroll
            for (int k = 0; k < 4; k++) pn[k] = __ldcs(nrow + 32 * k);

            // ---- encoder LIF step (warp-uniform spikes) ----
            bool es[4];
            #pragma unroll
            for (int f = 0; f < 4; f++) {
                float vd = fmaf(0.1f, c_in[f] - venc[f], venc[f]);
                es[f] = vd > 1.0f;
                venc[f] = es[f] ? 0.0f : vd;
            }

            // ---- recurrent LIF membrane update ----
            bool zn[4];
            #pragma unroll
            for (int k = 0; k < 4; k++) {
                float vd = fmaf(0.1f, cur[k] - v[k], v[k]);
                zn[k] = vd > 1.0f;
                v[k] = zn[k] ? 0.0f : vd;
                cur[k] *= 0.8f;
            }

            // ---- sparse current accumulation, dual packed accumulators ----
            unsigned long long c01  = pk2(cur[0], cur[1]);
            unsigned long long c23  = pk2(cur[2], cur[3]);
            unsigned long long c01b = 0ull;   // packed {0.f, 0.f}
            unsigned long long c23b = 0ull;

            // input channel rows (warp-uniform predicates)
            #pragma unroll
            for (int f = 0; f < 4; f++) {
                if (es[f]) {
                    ulonglong2 w = srec[rowe[f] + lane];
                    c01 = addx2(c01, w.x);
                    c23 = addx2(c23, w.y);
                }
            }
            // recurrent rows over z_prev; bits warp-uniform (ballot), so the
            // control flow is non-divergent. Unroll-by-2: both LDS.128 issue
            // before their dependent adds (2x MLP in the hot loop).
            #pragma unroll
            for (int k = 0; k < 4; k++) {
                unsigned bits = zb[k];
                const ulonglong2* rowp = srec + (32 * k) * 32 + lane;
                while (bits) {
                    int j1 = __ffs(bits) - 1; bits &= bits - 1;
                    ulonglong2 w1 = rowp[j1 * 32];
                    if (bits) {
                        int j2 = __ffs(bits) - 1; bits &= bits - 1;
                        ulonglong2 w2 = rowp[j2 * 32];
                        c01b = addx2(c01b, w2.x);
                        c23b = addx2(c23b, w2.y);
                    }
                    c01 = addx2(c01, w1.x);
                    c23 = addx2(c23, w1.y);
                }
            }
            c01 = addx2(c01, c01b);
            c23 = addx2(c23, c23b);
            upk2(c01, cur[0], cur[1]);
            upk2(c23, cur[2], cur[3]);

            // ---- publish new spikes ----
            #pragma unroll
            for (int k = 0; k < 4; k++)
                zb[k] = __ballot_sync(0xffffffffu, zn[k]);

            // ---- readout drive: (z_new * mask) @ w_out.T ----
            float d0 = 0.f, d1 = 0.f;
            #pragma unroll
            for (int k = 0; k < 4; k++) {
                float mv = zn[k] ? pm[k] : 0.0f;
                d0 = fmaf(mv, wo0[k], d0);
                d1 = fmaf(mv, wo1[k], d1);
            }
            unsigned long long d01 = pk2(d0, d1);
            #pragma unroll
            for (int off = 16; off; off >>= 1)
                d01 = addx2(d01, __shfl_xor_sync(0xffffffffu, d01, off));
            upk2(d01, d0, d1);

            // ---- LI readout (vo uses OLD io, matching reference) ----
            vo0 = fmaf(0.1f, io0 - vo0, vo0);
            vo1 = fmaf(0.1f, io1 - vo1, vo1);
            io0 = fmaf(0.8f, io0, d0);
            io1 = fmaf(0.8f, io1, d1);
            m0 = fmaxf(m0, vo0);
            m1 = fmaxf(m1, vo1);

            #pragma unroll
            for (int k = 0; k < 4; k++) pm[k] = pn[k];
            mrow = nrow;
        }

        if (lane == 0) {
            float mm = fmaxf(m0, m1);
            float e0 = expf(m0 - mm);
            float e1 = expf(m1 - mm);
            float inv = 1.0f / (e0 + e1);
            out[(size_t)b * 2 + 0] = e0 * inv;
            out[(size_t)b * 2 + 1] = e1 * inv;
        }
    }
}

extern "C" void kernel_launch(void* const* d_in, const int* in_sizes, int n_in,
                              void* d_out, int out_size) {
    const float* x     = (const float*)d_in[0];  // (B, 4)
    const float* w_in  = (const float*)d_in[1];  // (128, 8)
    const float* w_rec = (const float*)d_in[2];  // (128, 128)
    const float* w_out = (const float*)d_in[3];  // (2, 128)
    const float* mask  = (const float*)d_in[4];  // (40, B, 128)
    float* out = (float*)d_out;

    const int B = in_sizes[0] / 4;

    cudaFuncSetAttribute(snn_kernel,
                         cudaFuncAttributeMaxDynamicSharedMemorySize,
                         ROWS * HID * (int)sizeof(float));

    prep_kernel<<<(HID * HID + HID * 8 + 255) / 256, 256>>>(w_rec, w_in);

    snn_kernel<<<NCTA, TPB, ROWS * HID * sizeof(float)>>>(
        x, w_out, mask, out, B);
}